// round 13
// baseline (speedup 1.0000x reference)
#include <cuda_runtime.h>
#include <cuda_fp16.h>

// ---------------------------------------------------------------------------
// Shifted-window 3D attention — all-fp16 tensor-core pipeline (fp32 accum).
// Round 13: attn softmax moved to fp16x2 exp2 (half the MUFU work) and
// row-sums computed by a ones-column mma (no sum FADDs, no shuffle reduce).
// GEMMs identical to round 12.
// ---------------------------------------------------------------------------

#define NWIN   128
#define NTOK   392
#define NHD    8
#define DH     32
#define CCH    256
#define MROWS  (NWIN * NTOK)        // 50176
#define QKVN   768

#define LOG2E  1.4426950408889634f
#define MASKC  (-144.26950408889634f)   // -100 * log2(e)
#define ONES2  0x3C003C00u              // half2(1.0, 1.0)

// Scratch (device globals). g_qh padded 8 rows (128 uints) for the last
// q-tile over-read.
__device__ unsigned g_qh [NWIN * NHD * NTOK * (DH / 2) + 128]; // q fp16 pairs
__device__ unsigned g_kh [NWIN * NHD * NTOK * (DH / 2)];       // k fp16 pairs
__device__ float    g_v  [NWIN * NHD * NTOK * DH];
__device__ unsigned g_aoh[MROWS * (CCH / 2)];                  // attn out, fp16 pairs
__device__ __half   g_biash[NHD * NTOK * NTOK];
__device__ unsigned g_wq_h[(256 / 2) * QKVN];   // qkv_w fp16 pairs, [k/2][n]
__device__ unsigned g_wp_h[(256 / 2) * CCH];    // proj_w fp16 pairs, [k/2][n]

__device__ __forceinline__ void mma16h(float* c, unsigned a0, unsigned a1,
                                       unsigned a2, unsigned a3,
                                       unsigned b0, unsigned b1) {
    asm volatile(
        "mma.sync.aligned.m16n8k16.row.col.f32.f16.f16.f32 "
        "{%0,%1,%2,%3},{%4,%5,%6,%7},{%8,%9},{%0,%1,%2,%3};"
        : "+f"(c[0]), "+f"(c[1]), "+f"(c[2]), "+f"(c[3])
        : "r"(a0), "r"(a1), "r"(a2), "r"(a3), "r"(b0), "r"(b1));
}

__device__ __forceinline__ unsigned packh2(float lo, float hi) {
    __half2 h = __floats2half2_rn(lo, hi);
    return *(unsigned*)&h;
}

__device__ __forceinline__ unsigned h2exp2(unsigned x) {
    unsigned r;
    asm("ex2.approx.f16x2 %0, %1;" : "=r"(r) : "r"(x));
    return r;
}

// ---------------------------------------------------------------------------
// Relative-position bias precompute (log2e-scaled, fp16).
// ---------------------------------------------------------------------------
__global__ void bias_kernel(const float* __restrict__ rpb) {
    int idx = blockIdx.x * 256 + threadIdx.x;
    if (idx >= NHD * NTOK * NTOK) return;
    int m = idx % NTOK;
    int t = idx / NTOK;
    int n = t % NTOK;
    int h = t / NTOK;
    int i1 = n / 49, r1 = n - i1 * 49, j1 = r1 / 7, k1 = r1 - j1 * 7;
    int i2 = m / 49, r2 = m - i2 * 49, j2 = r2 / 7, k2 = r2 - j2 * 7;
    int tb = (i1 - i2 + 7) * 169 + (j1 - j2 + 6) * 13 + (k1 - k2 + 6);
    g_biash[idx] = __float2half(rpb[tb * 8 + h] * LOG2E);
}

// Weight pre-convert: fp32 [n][k] -> fp16 k-pairs [k/2][n]
__global__ void cvt_w_kernel(const float* __restrict__ wq,
                             const float* __restrict__ wp) {
    int idx = blockIdx.x * 256 + threadIdx.x;
    if (idx < 128 * QKVN) {
        int kp = idx / QKVN, n = idx - kp * QKVN;
        g_wq_h[idx] = packh2(wq[n * 256 + 2 * kp], wq[n * 256 + 2 * kp + 1]);
    } else {
        int i2 = idx - 128 * QKVN;
        if (i2 < 128 * CCH) {
            int kp = i2 >> 8, n = i2 & 255;
            g_wp_h[i2] = packh2(wp[n * 256 + 2 * kp], wp[n * 256 + 2 * kp + 1]);
        }
    }
}

// ---------------------------------------------------------------------------
// fp16 GEMM tiles: BM=128, BN=64, BK=16, 256 threads (8 warps, 32x32 each).
// ---------------------------------------------------------------------------
#define HA_STR 12
#define HB_STR 72

__global__ void __launch_bounds__(256, 4) qkv_gemm(
    const float* __restrict__ x, const float* __restrict__ bq)
{
    __shared__ __align__(16) unsigned As[2][128 * HA_STR];
    __shared__ __align__(16) unsigned Bs[2][8 * HB_STR];

    int tid  = threadIdx.x;
    int row0 = blockIdx.x * 128;
    int col0 = blockIdx.y * 64;
    int lr   = tid >> 2, kq = tid & 3;

    const float* ap[2];
    #pragma unroll
    for (int h = 0; h < 2; ++h) {
        int r   = row0 + lr + h * 64;
        int win = r / NTOK, n = r - win * NTOK;
        int wt = win >> 6, wh = (win >> 3) & 7, ww = win & 7;
        int i = n / 49, rem = n - i * 49, j = rem / 7, kk = rem - j * 7;
        int z  = (wt * 8 + i + 4) & 15;
        int y  = wh * 7 + j + 3;  if (y  >= 56) y  -= 56;
        int xx = ww * 7 + kk + 3; if (xx >= 56) xx -= 56;
        ap[h] = x + (((z * 56 + y) * 56 + xx) << 8) + (kq << 2);
    }
    int bkr  = tid >> 5;            // 0..7  (k-pair row)
    int bnc2 = (tid & 31) * 2;      // 0..62 (n col, 2 at a time)
    const unsigned* wsrc = g_wq_h + col0 + bnc2;

    int warp = tid >> 5, lane = tid & 31;
    int wm = warp >> 1, wn = warp & 1;
    int g = lane >> 2, t4 = lane & 3;

    float acc[2][4][4] = {};

    {
        float4 a0 = *(const float4*)(ap[0]);
        float4 a1 = *(const float4*)(ap[1]);
        uint2  bv = *(const uint2*)(wsrc + bkr * QKVN);
        As[0][lr * HA_STR + kq * 2]            = packh2(a0.x, a0.y);
        As[0][lr * HA_STR + kq * 2 + 1]        = packh2(a0.z, a0.w);
        As[0][(lr + 64) * HA_STR + kq * 2]     = packh2(a1.x, a1.y);
        As[0][(lr + 64) * HA_STR + kq * 2 + 1] = packh2(a1.z, a1.w);
        *(uint2*)&Bs[0][bkr * HB_STR + bnc2] = bv;
    }
    __syncthreads();

    for (int kt = 0; kt < 16; ++kt) {
        int buf = kt & 1;
        float4 a0n, a1n;
        uint2  bvn;
        if (kt < 15) {
            a0n = *(const float4*)(ap[0] + (kt + 1) * 16);
            a1n = *(const float4*)(ap[1] + (kt + 1) * 16);
            bvn = *(const uint2*)(wsrc + ((kt + 1) * 8 + bkr) * QKVN);
        }
        unsigned afr[2][4], bfr[4][2];
        #pragma unroll
        for (int mt = 0; mt < 2; ++mt) {
            int m0 = wm * 32 + mt * 16;
            const unsigned* base = &As[buf][0];
            afr[mt][0] = base[(m0 + g)     * HA_STR + t4];
            afr[mt][1] = base[(m0 + g + 8) * HA_STR + t4];
            afr[mt][2] = base[(m0 + g)     * HA_STR + t4 + 4];
            afr[mt][3] = base[(m0 + g + 8) * HA_STR + t4 + 4];
        }
        #pragma unroll
        for (int nt = 0; nt < 4; ++nt) {
            int n0 = wn * 32 + nt * 8;
            bfr[nt][0] = Bs[buf][t4 * HB_STR + n0 + g];
            bfr[nt][1] = Bs[buf][(t4 + 4) * HB_STR + n0 + g];
        }
        #pragma unroll
        for (int mt = 0; mt < 2; ++mt)
            #pragma unroll
            for (int nt = 0; nt < 4; ++nt)
                mma16h(acc[mt][nt], afr[mt][0], afr[mt][1], afr[mt][2],
                       afr[mt][3], bfr[nt][0], bfr[nt][1]);

        if (kt < 15) {
            int nb = buf ^ 1;
            As[nb][lr * HA_STR + kq * 2]            = packh2(a0n.x, a0n.y);
            As[nb][lr * HA_STR + kq * 2 + 1]        = packh2(a0n.z, a0n.w);
            As[nb][(lr + 64) * HA_STR + kq * 2]     = packh2(a1n.x, a1n.y);
            As[nb][(lr + 64) * HA_STR + kq * 2 + 1] = packh2(a1n.z, a1n.w);
            *(uint2*)&Bs[nb][bkr * HB_STR + bnc2] = bvn;
            __syncthreads();
        }
    }

    // epilogue: split to q/k/v (head-major). q pre-scaled by dh^-0.5 * log2e.
    int part = col0 >> 8;
    float scale = (part == 0) ? (0.17677669529663687f * LOG2E) : 1.0f;
    #pragma unroll
    for (int mt = 0; mt < 2; ++mt) {
        #pragma unroll
        for (int half = 0; half < 2; ++half) {
            int rg  = row0 + wm * 32 + mt * 16 + g + half * 8;
            int win = rg / NTOK, n = rg - win * NTOK;
            #pragma unroll
            for (int nt = 0; nt < 4; ++nt) {
                int c = col0 + wn * 32 + nt * 8 + 2 * t4;
                int head = (c >> 5) & 7, d = c & 31;
                float r0 = (acc[mt][nt][half * 2 + 0] + bq[c])     * scale;
                float r1 = (acc[mt][nt][half * 2 + 1] + bq[c + 1]) * scale;
                size_t bhn = ((size_t)(win * 8 + head) * NTOK + n);
                if (part < 2) {
                    unsigned* dsth = (part == 0) ? g_qh : g_kh;
                    dsth[bhn * 16 + (d >> 1)] = packh2(r0, r1);
                } else {
                    *(float2*)&g_v[bhn * 32 + d] = make_float2(r0, r1);
                }
            }
        }
    }
}

// ---------------------------------------------------------------------------
// Flash attention: 3 blocks/SM, fp16x2 exp2 softmax, row-sums via ones-mma.
// K fp16 half2 [m][d/2] stride 20; V fp16 half2 [d][m/2] stride 196 (+8 pad).
// ---------------------------------------------------------------------------
#define KH_STR 20
#define V_STR2 196
#define ATTN_SMEM_BYTES ((NTOK * KH_STR + 32 * V_STR2 + 8 + NTOK) * 4)

__global__ void __launch_bounds__(256, 3) attn_kernel() {
    extern __shared__ float sm[];
    unsigned* Kh = (unsigned*)sm;
    unsigned* Vh = Kh + NTOK * KH_STR;
    int*      lb = (int*)(Vh + 32 * V_STR2 + 8);

    int tid = threadIdx.x;
    int bh  = blockIdx.x;
    int win = bh >> 3, head = bh & 7;

    const unsigned* kg = g_kh + (size_t)bh * NTOK * 16;
    const float*    vg = g_v  + (size_t)bh * NTOK * DH;
    const unsigned* qg = g_qh + (size_t)bh * NTOK * 16;

    for (int idx = tid; idx < NTOK * 16; idx += 256) {
        int m = idx >> 4, dp = idx & 15;
        Kh[m * KH_STR + dp] = kg[idx];
    }
    for (int idx = tid; idx < (NTOK / 2) * DH; idx += 256) {
        int mp = idx >> 5, d = idx & 31;
        float v0 = vg[(2 * mp)     * DH + d];
        float v1 = vg[(2 * mp + 1) * DH + d];
        Vh[d * V_STR2 + mp] = packh2(v0, v1);
    }
    int wt = win >> 6, wh = (win >> 3) & 7, ww = win & 7;
    for (int nn = tid; nn < NTOK; nn += 256) {
        int i = nn / 49, rem = nn - i * 49, j = rem / 7, k2 = rem - j * 7;
        int z = wt * 8 + i, y = wh * 7 + j, xx = ww * 7 + k2;
        int lt = (z  < 8)  ? 0 : ((z  < 12) ? 1 : 2);
        int lh = (y  < 49) ? 0 : ((y  < 53) ? 1 : 2);
        int lw = (xx < 49) ? 0 : ((xx < 53) ? 1 : 2);
        lb[nn] = lt * 9 + lh * 3 + lw;
    }
    __syncthreads();

    int w = tid >> 5, lane = tid & 31;
    int g = lane >> 2, t4 = lane & 3;
    const __half* brow = g_biash + (size_t)head * NTOK * NTOK;
    int mofs = 2 * t4;

    for (int qt = w; qt < 25; qt += 8) {
        int q0r = qt * 16;
        int n_g  = q0r + g;
        int n_g8 = n_g + 8;
        int nc_g  = (n_g  < NTOK) ? n_g  : NTOK - 1;
        int nc_g8 = (n_g8 < NTOK) ? n_g8 : NTOK - 1;
        int lbn_g  = lb[nc_g];
        int lbn_g8 = lb[nc_g8];
        const __half* bp_g  = brow + (size_t)nc_g  * NTOK;
        const __half* bp_g8 = brow + (size_t)nc_g8 * NTOK;

        unsigned qa0[4], qa1[4];
        {
            const unsigned* qb  = qg + (size_t)(q0r + g) * 16;
            const unsigned* qb8 = qb + 8 * 16;
            qa0[0] = qb [t4];      qa0[1] = qb8[t4];
            qa0[2] = qb [t4 + 4];  qa0[3] = qb8[t4 + 4];
            qa1[0] = qb [t4 + 8];  qa1[1] = qb8[t4 + 8];
            qa1[2] = qb [t4 + 12]; qa1[3] = qb8[t4 + 12];
        }

        float o[4][4] = {};
        float sacc[4] = {};          // row sums via ones-mma (all quad lanes equal)

        float2 pb0g  = __half22float2(*(const __half2*)(bp_g  + mofs));
        float2 pb1g  = __half22float2(*(const __half2*)(bp_g  + 8 + mofs));
        float2 pb0g8 = __half22float2(*(const __half2*)(bp_g8 + mofs));
        float2 pb1g8 = __half22float2(*(const __half2*)(bp_g8 + 8 + mofs));

        for (int jp = 0; jp < 24; ++jp) {
            int j0 = jp * 2, j1 = j0 + 1;
            float2 b0g = pb0g, b1g = pb1g, b0g8 = pb0g8, b1g8 = pb1g8;
            {
                int nj = (jp < 23) ? (j0 + 2) : 48;
                pb0g  = __half22float2(*(const __half2*)(bp_g  + nj * 8 + mofs));
                pb0g8 = __half22float2(*(const __half2*)(bp_g8 + nj * 8 + mofs));
                if (jp < 23) {
                    pb1g  = __half22float2(*(const __half2*)(bp_g  + nj * 8 + 8 + mofs));
                    pb1g8 = __half22float2(*(const __half2*)(bp_g8 + nj * 8 + 8 + mofs));
                }
            }

            float c0[4] = {0.f, 0.f, 0.f, 0.f};
            float c1[4] = {0.f, 0.f, 0.f, 0.f};
            {
                const unsigned* kr0 = Kh + (j0 * 8 + g) * KH_STR;
                const unsigned* kr1 = Kh + (j1 * 8 + g) * KH_STR;
                mma16h(c0, qa0[0], qa0[1], qa0[2], qa0[3], kr0[t4],     kr0[t4 + 4]);
                mma16h(c0, qa1[0], qa1[1], qa1[2], qa1[3], kr0[t4 + 8], kr0[t4 + 12]);
                mma16h(c1, qa0[0], qa0[1], qa0[2], qa0[3], kr1[t4],     kr1[t4 + 4]);
                mma16h(c1, qa1[0], qa1[1], qa1[2], qa1[3], kr1[t4 + 8], kr1[t4 + 12]);
            }

            int m0 = j0 * 8 + mofs, m1 = j1 * 8 + mofs;
            int lm00 = lb[m0], lm01 = lb[m0 + 1];
            int lm10 = lb[m1], lm11 = lb[m1 + 1];

            float s00 = c0[0] + b0g.x  + ((lm00 != lbn_g)  ? MASKC : 0.f);
            float s01 = c0[1] + b0g.y  + ((lm01 != lbn_g)  ? MASKC : 0.f);
            float s02 = c0[2] + b0g8.x + ((lm00 != lbn_g8) ? MASKC : 0.f);
            float s03 = c0[3] + b0g8.y + ((lm01 != lbn_g8) ? MASKC : 0.f);
            float s10 = c1[0] + b1g.x  + ((lm10 != lbn_g)  ? MASKC : 0.f);
            float s11 = c1[1] + b1g.y  + ((lm11 != lbn_g)  ? MASKC : 0.f);
            float s12 = c1[2] + b1g8.x + ((lm10 != lbn_g8) ? MASKC : 0.f);
            float s13 = c1[3] + b1g8.y + ((lm11 != lbn_g8) ? MASKC : 0.f);

            // pack scores to half2, exponentiate in fp16x2 (half the MUFU ops)
            unsigned a0 = h2exp2(packh2(s00, s01));
            unsigned a1 = h2exp2(packh2(s02, s03));
            unsigned a2 = h2exp2(packh2(s10, s11));
            unsigned a3 = h2exp2(packh2(s12, s13));

            // row sums via ones-column mma (exact, quad-reduced by HW)
            mma16h(sacc, a0, a1, a2, a3, ONES2, ONES2);

            #pragma unroll
            for (int jd = 0; jd < 4; ++jd) {
                int vrow = (jd * 8 + g) * V_STR2 + j0 * 4 + t4;
                mma16h(o[jd], a0, a1, a2, a3, Vh[vrow], Vh[vrow + 4]);
            }
        }

        // tail tile j=48 (k=8..15 zeroed: a2=a3=0 AS P VALUES, B tail reg 0)
        {
            const int j = 48;
            float c[4] = {0.f, 0.f, 0.f, 0.f};
            const unsigned* kr = Kh + (j * 8 + g) * KH_STR;
            mma16h(c, qa0[0], qa0[1], qa0[2], qa0[3], kr[t4],     kr[t4 + 4]);
            mma16h(c, qa1[0], qa1[1], qa1[2], qa1[3], kr[t4 + 8], kr[t4 + 12]);

            int m0 = j * 8 + mofs;
            int lm0 = lb[m0], lm1 = lb[m0 + 1];
            float s0 = c[0] + pb0g.x  + ((lm0 != lbn_g)  ? MASKC : 0.f);
            float s1 = c[1] + pb0g.y  + ((lm1 != lbn_g)  ? MASKC : 0.f);
            float s2 = c[2] + pb0g8.x + ((lm0 != lbn_g8) ? MASKC : 0.f);
            float s3 = c[3] + pb0g8.y + ((lm1 != lbn_g8) ? MASKC : 0.f);

            unsigned a0 = h2exp2(packh2(s0, s1));
            unsigned a1 = h2exp2(packh2(s2, s3));

            mma16h(sacc, a0, a1, 0u, 0u, ONES2, ONES2);

            #pragma unroll
            for (int jd = 0; jd < 4; ++jd) {
                int vrow = (jd * 8 + g) * V_STR2 + j * 4 + t4;
                mma16h(o[jd], a0, a1, 0u, 0u, Vh[vrow], 0u);
            }
        }

        float inv_g  = 1.f / sacc[0];
        float inv_g8 = 1.f / sacc[2];

        if (n_g < NTOK) {
            unsigned* ob = g_aoh + (size_t)(win * NTOK + n_g) * 128 + head * 16;
            #pragma unroll
            for (int jd = 0; jd < 4; ++jd)
                ob[jd * 4 + t4] = packh2(o[jd][0] * inv_g, o[jd][1] * inv_g);
        }
        if (n_g8 < NTOK) {
            unsigned* ob = g_aoh + (size_t)(win * NTOK + n_g8) * 128 + head * 16;
            #pragma unroll
            for (int jd = 0; jd < 4; ++jd)
                ob[jd * 4 + t4] = packh2(o[jd][2] * inv_g8, o[jd][3] * inv_g8);
        }
    }
}

// ---------------------------------------------------------------------------
// Projection GEMM (fp16): A = g_aoh (fp16 pairs), B = g_wp_h.
// Fused reverse-window + reverse-roll scatter.
// ---------------------------------------------------------------------------
__global__ void __launch_bounds__(256) proj_gemm(
    const float* __restrict__ bp, float* __restrict__ out)
{
    __shared__ __align__(16) unsigned As[2][128 * HA_STR];
    __shared__ __align__(16) unsigned Bs[2][8 * HB_STR];

    int tid  = threadIdx.x;
    int row0 = blockIdx.x * 128;
    int col0 = blockIdx.y * 64;
    int lr   = tid >> 2, kq = tid & 3;

    const unsigned* ap[2];
    ap[0] = g_aoh + (size_t)(row0 + lr) * 128 + kq * 2;
    ap[1] = g_aoh + (size_t)(row0 + lr + 64) * 128 + kq * 2;
    int bkr  = tid >> 5;
    int bnc2 = (tid & 31) * 2;
    const unsigned* wsrc = g_wp_h + col0 + bnc2;

    int warp = tid >> 5, lane = tid & 31;
    int wm = warp >> 1, wn = warp & 1;
    int g = lane >> 2, t4 = lane & 3;

    float acc[2][4][4] = {};

    {
        uint2 a0 = *(const uint2*)(ap[0]);
        uint2 a1 = *(const uint2*)(ap[1]);
        uint2 bv = *(const uint2*)(wsrc + bkr * CCH);
        *(uint2*)&As[0][lr * HA_STR + kq * 2]        = a0;
        *(uint2*)&As[0][(lr + 64) * HA_STR + kq * 2] = a1;
        *(uint2*)&Bs[0][bkr * HB_STR + bnc2]         = bv;
    }
    __syncthreads();

    for (int kt = 0; kt < 16; ++kt) {
        int buf = kt & 1;
        uint2 a0n, a1n, bvn;
        if (kt < 15) {
            a0n = *(const uint2*)(ap[0] + (kt + 1) * 8);
            a1n = *(const uint2*)(ap[1] + (kt + 1) * 8);
            bvn = *(const uint2*)(wsrc + ((kt + 1) * 8 + bkr) * CCH);
        }
        unsigned afr[2][4], bfr[4][2];
        #pragma unroll
        for (int mt = 0; mt < 2; ++mt) {
            int m0 = wm * 32 + mt * 16;
            const unsigned* base = &As[buf][0];
            afr[mt][0] = base[(m0 + g)     * HA_STR + t4];
            afr[mt][1] = base[(m0 + g + 8) * HA_STR + t4];
            afr[mt][2] = base[(m0 + g)     * HA_STR + t4 + 4];
            afr[mt][3] = base[(m0 + g + 8) * HA_STR + t4 + 4];
        }
        #pragma unroll
        for (int nt = 0; nt < 4; ++nt) {
            int n0 = wn * 32 + nt * 8;
            bfr[nt][0] = Bs[buf][t4 * HB_STR + n0 + g];
            bfr[nt][1] = Bs[buf][(t4 + 4) * HB_STR + n0 + g];
        }
        #pragma unroll
        for (int mt = 0; mt < 2; ++mt)
            #pragma unroll
            for (int nt = 0; nt < 4; ++nt)
                mma16h(acc[mt][nt], afr[mt][0], afr[mt][1], afr[mt][2],
                       afr[mt][3], bfr[nt][0], bfr[nt][1]);

        if (kt < 15) {
            int nb = buf ^ 1;
            *(uint2*)&As[nb][lr * HA_STR + kq * 2]        = a0n;
            *(uint2*)&As[nb][(lr + 64) * HA_STR + kq * 2] = a1n;
            *(uint2*)&Bs[nb][bkr * HB_STR + bnc2]         = bvn;
            __syncthreads();
        }
    }

    #pragma unroll
    for (int mt = 0; mt < 2; ++mt) {
        #pragma unroll
        for (int half = 0; half < 2; ++half) {
            int rg  = row0 + wm * 32 + mt * 16 + g + half * 8;
            int win = rg / NTOK, n = rg - win * NTOK;
            int wt = win >> 6, wh = (win >> 3) & 7, ww = win & 7;
            int i = n / 49, rem = n - i * 49, j = rem / 7, kk = rem - j * 7;
            int z  = (wt * 8 + i + 4) & 15;
            int y  = wh * 7 + j + 3;  if (y  >= 56) y  -= 56;
            int xx = ww * 7 + kk + 3; if (xx >= 56) xx -= 56;
            float* dst = out + (((z * 56 + y) * 56 + xx) << 8);
            #pragma unroll
            for (int nt = 0; nt < 4; ++nt) {
                int c = col0 + wn * 32 + nt * 8 + 2 * t4;
                float v0 = acc[mt][nt][half * 2 + 0] + bp[c];
                float v1 = acc[mt][nt][half * 2 + 1] + bp[c + 1];
                *(float2*)&dst[c] = make_float2(v0, v1);
            }
        }
    }
}

// ---------------------------------------------------------------------------
extern "C" void kernel_launch(void* const* d_in, const int* in_sizes, int n_in,
                              void* d_out, int out_size)
{
    (void)in_sizes; (void)n_in; (void)out_size;
    const float* x      = (const float*)d_in[0];
    const float* qkv_w  = (const float*)d_in[1];
    const float* qkv_b  = (const float*)d_in[2];
    const float* proj_w = (const float*)d_in[3];
    const float* proj_b = (const float*)d_in[4];
    const float* rpb    = (const float*)d_in[5];
    float* out = (float*)d_out;

    cudaFuncSetAttribute(attn_kernel,
                         cudaFuncAttributeMaxDynamicSharedMemorySize,
                         ATTN_SMEM_BYTES);

    bias_kernel<<<(NHD * NTOK * NTOK + 255) / 256, 256>>>(rpb);
    cvt_w_kernel<<<(128 * QKVN + 128 * CCH + 255) / 256, 256>>>(qkv_w, proj_w);

    dim3 gq(MROWS / 128, QKVN / 64);
    qkv_gemm<<<gq, 256>>>(x, qkv_b);

    attn_kernel<<<NWIN * NHD, 256, ATTN_SMEM_BYTES>>>();

    dim3 gp(MROWS / 128, CCH / 64);
    proj_gemm<<<gp, 256>>>(proj_b, out);
}

// round 14
// speedup vs baseline: 1.1251x; 1.1251x over previous
#include <cuda_runtime.h>
#include <cuda_fp16.h>

// ---------------------------------------------------------------------------
// Shifted-window 3D attention — all-fp16 tensor-core pipeline (fp32 accum).
// Round 14: GEMMs widened to BN=128 with 512-thread blocks (halves A-side
// L2 traffic + sync count; per-warp tile unchanged). attn = round-13 version.
// ---------------------------------------------------------------------------

#define NWIN   128
#define NTOK   392
#define NHD    8
#define DH     32
#define CCH    256
#define MROWS  (NWIN * NTOK)        // 50176
#define QKVN   768

#define LOG2E  1.4426950408889634f
#define MASKC  (-144.26950408889634f)   // -100 * log2(e)
#define ONES2  0x3C003C00u              // half2(1.0, 1.0)

// Scratch (device globals). g_qh padded 8 rows (128 uints) for the last
// q-tile over-read.
__device__ unsigned g_qh [NWIN * NHD * NTOK * (DH / 2) + 128]; // q fp16 pairs
__device__ unsigned g_kh [NWIN * NHD * NTOK * (DH / 2)];       // k fp16 pairs
__device__ float    g_v  [NWIN * NHD * NTOK * DH];
__device__ unsigned g_aoh[MROWS * (CCH / 2)];                  // attn out, fp16 pairs
__device__ __half   g_biash[NHD * NTOK * NTOK];
__device__ unsigned g_wq_h[(256 / 2) * QKVN];   // qkv_w fp16 pairs, [k/2][n]
__device__ unsigned g_wp_h[(256 / 2) * CCH];    // proj_w fp16 pairs, [k/2][n]

__device__ __forceinline__ void mma16h(float* c, unsigned a0, unsigned a1,
                                       unsigned a2, unsigned a3,
                                       unsigned b0, unsigned b1) {
    asm volatile(
        "mma.sync.aligned.m16n8k16.row.col.f32.f16.f16.f32 "
        "{%0,%1,%2,%3},{%4,%5,%6,%7},{%8,%9},{%0,%1,%2,%3};"
        : "+f"(c[0]), "+f"(c[1]), "+f"(c[2]), "+f"(c[3])
        : "r"(a0), "r"(a1), "r"(a2), "r"(a3), "r"(b0), "r"(b1));
}

__device__ __forceinline__ unsigned packh2(float lo, float hi) {
    __half2 h = __floats2half2_rn(lo, hi);
    return *(unsigned*)&h;
}

__device__ __forceinline__ unsigned h2exp2(unsigned x) {
    unsigned r;
    asm("ex2.approx.f16x2 %0, %1;" : "=r"(r) : "r"(x));
    return r;
}

// ---------------------------------------------------------------------------
// Relative-position bias precompute (log2e-scaled, fp16).
// ---------------------------------------------------------------------------
__global__ void bias_kernel(const float* __restrict__ rpb) {
    int idx = blockIdx.x * 256 + threadIdx.x;
    if (idx >= NHD * NTOK * NTOK) return;
    int m = idx % NTOK;
    int t = idx / NTOK;
    int n = t % NTOK;
    int h = t / NTOK;
    int i1 = n / 49, r1 = n - i1 * 49, j1 = r1 / 7, k1 = r1 - j1 * 7;
    int i2 = m / 49, r2 = m - i2 * 49, j2 = r2 / 7, k2 = r2 - j2 * 7;
    int tb = (i1 - i2 + 7) * 169 + (j1 - j2 + 6) * 13 + (k1 - k2 + 6);
    g_biash[idx] = __float2half(rpb[tb * 8 + h] * LOG2E);
}

// Weight pre-convert: fp32 [n][k] -> fp16 k-pairs [k/2][n]
__global__ void cvt_w_kernel(const float* __restrict__ wq,
                             const float* __restrict__ wp) {
    int idx = blockIdx.x * 256 + threadIdx.x;
    if (idx < 128 * QKVN) {
        int kp = idx / QKVN, n = idx - kp * QKVN;
        g_wq_h[idx] = packh2(wq[n * 256 + 2 * kp], wq[n * 256 + 2 * kp + 1]);
    } else {
        int i2 = idx - 128 * QKVN;
        if (i2 < 128 * CCH) {
            int kp = i2 >> 8, n = i2 & 255;
            g_wp_h[i2] = packh2(wp[n * 256 + 2 * kp], wp[n * 256 + 2 * kp + 1]);
        }
    }
}

// ---------------------------------------------------------------------------
// fp16 GEMM tiles: BM=128, BN=128, BK=16, 512 threads (16 warps, 32x32 each).
// As half2 [m][8] stride 12; Bs half2 [8][128] stride 136 (conflict-free).
// ---------------------------------------------------------------------------
#define HA_STR  12
#define HB2_STR 136

__global__ void __launch_bounds__(512, 2) qkv_gemm(
    const float* __restrict__ x, const float* __restrict__ bq)
{
    __shared__ __align__(16) unsigned As[2][128 * HA_STR];
    __shared__ __align__(16) unsigned Bs[2][8 * HB2_STR];

    int tid  = threadIdx.x;
    int row0 = blockIdx.x * 128;
    int col0 = blockIdx.y * 128;
    int lr   = tid >> 2, kq = tid & 3;

    // gather pointer for row lr
    const float* ap;
    {
        int r   = row0 + lr;
        int win = r / NTOK, n = r - win * NTOK;
        int wt = win >> 6, wh = (win >> 3) & 7, ww = win & 7;
        int i = n / 49, rem = n - i * 49, j = rem / 7, kk = rem - j * 7;
        int z  = (wt * 8 + i + 4) & 15;
        int y  = wh * 7 + j + 3;  if (y  >= 56) y  -= 56;
        int xx = ww * 7 + kk + 3; if (xx >= 56) xx -= 56;
        ap = x + (((z * 56 + y) * 56 + xx) << 8) + (kq << 2);
    }
    int bkr  = tid >> 6;            // 0..7  (k-pair row)
    int bnc2 = (tid & 63) * 2;      // 0..126 (n col, 2 at a time)
    const unsigned* wsrc = g_wq_h + col0 + bnc2;

    int warp = tid >> 5, lane = tid & 31;
    int wm = warp >> 2, wn = warp & 3;
    int g = lane >> 2, t4 = lane & 3;

    float acc[2][4][4] = {};

    {
        float4 a0 = *(const float4*)(ap);
        uint2  bv = *(const uint2*)(wsrc + bkr * QKVN);
        As[0][lr * HA_STR + kq * 2]     = packh2(a0.x, a0.y);
        As[0][lr * HA_STR + kq * 2 + 1] = packh2(a0.z, a0.w);
        *(uint2*)&Bs[0][bkr * HB2_STR + bnc2] = bv;
    }
    __syncthreads();

    for (int kt = 0; kt < 16; ++kt) {
        int buf = kt & 1;
        float4 a0n;
        uint2  bvn;
        if (kt < 15) {
            a0n = *(const float4*)(ap + (kt + 1) * 16);
            bvn = *(const uint2*)(wsrc + ((kt + 1) * 8 + bkr) * QKVN);
        }
        unsigned afr[2][4], bfr[4][2];
        #pragma unroll
        for (int mt = 0; mt < 2; ++mt) {
            int m0 = wm * 32 + mt * 16;
            const unsigned* base = &As[buf][0];
            afr[mt][0] = base[(m0 + g)     * HA_STR + t4];
            afr[mt][1] = base[(m0 + g + 8) * HA_STR + t4];
            afr[mt][2] = base[(m0 + g)     * HA_STR + t4 + 4];
            afr[mt][3] = base[(m0 + g + 8) * HA_STR + t4 + 4];
        }
        #pragma unroll
        for (int nt = 0; nt < 4; ++nt) {
            int n0 = wn * 32 + nt * 8;
            bfr[nt][0] = Bs[buf][t4 * HB2_STR + n0 + g];
            bfr[nt][1] = Bs[buf][(t4 + 4) * HB2_STR + n0 + g];
        }
        #pragma unroll
        for (int mt = 0; mt < 2; ++mt)
            #pragma unroll
            for (int nt = 0; nt < 4; ++nt)
                mma16h(acc[mt][nt], afr[mt][0], afr[mt][1], afr[mt][2],
                       afr[mt][3], bfr[nt][0], bfr[nt][1]);

        if (kt < 15) {
            int nb = buf ^ 1;
            As[nb][lr * HA_STR + kq * 2]     = packh2(a0n.x, a0n.y);
            As[nb][lr * HA_STR + kq * 2 + 1] = packh2(a0n.z, a0n.w);
            *(uint2*)&Bs[nb][bkr * HB2_STR + bnc2] = bvn;
            __syncthreads();
        }
    }

    // epilogue: split to q/k/v (head-major). q pre-scaled by dh^-0.5 * log2e.
    int part = col0 >> 8;
    float scale = (part == 0) ? (0.17677669529663687f * LOG2E) : 1.0f;
    #pragma unroll
    for (int mt = 0; mt < 2; ++mt) {
        #pragma unroll
        for (int half = 0; half < 2; ++half) {
            int rg  = row0 + wm * 32 + mt * 16 + g + half * 8;
            int win = rg / NTOK, n = rg - win * NTOK;
            #pragma unroll
            for (int nt = 0; nt < 4; ++nt) {
                int c = col0 + wn * 32 + nt * 8 + 2 * t4;
                int head = (c >> 5) & 7, d = c & 31;
                float r0 = (acc[mt][nt][half * 2 + 0] + bq[c])     * scale;
                float r1 = (acc[mt][nt][half * 2 + 1] + bq[c + 1]) * scale;
                size_t bhn = ((size_t)(win * 8 + head) * NTOK + n);
                if (part < 2) {
                    unsigned* dsth = (part == 0) ? g_qh : g_kh;
                    dsth[bhn * 16 + (d >> 1)] = packh2(r0, r1);
                } else {
                    *(float2*)&g_v[bhn * 32 + d] = make_float2(r0, r1);
                }
            }
        }
    }
}

// ---------------------------------------------------------------------------
// Flash attention (round-13: fp16x2 exp2 softmax, ones-mma row sums,
// 3 blocks/SM).
// ---------------------------------------------------------------------------
#define KH_STR 20
#define V_STR2 196
#define ATTN_SMEM_BYTES ((NTOK * KH_STR + 32 * V_STR2 + 8 + NTOK) * 4)

__global__ void __launch_bounds__(256, 3) attn_kernel() {
    extern __shared__ float sm[];
    unsigned* Kh = (unsigned*)sm;
    unsigned* Vh = Kh + NTOK * KH_STR;
    int*      lb = (int*)(Vh + 32 * V_STR2 + 8);

    int tid = threadIdx.x;
    int bh  = blockIdx.x;
    int win = bh >> 3, head = bh & 7;

    const unsigned* kg = g_kh + (size_t)bh * NTOK * 16;
    const float*    vg = g_v  + (size_t)bh * NTOK * DH;
    const unsigned* qg = g_qh + (size_t)bh * NTOK * 16;

    for (int idx = tid; idx < NTOK * 16; idx += 256) {
        int m = idx >> 4, dp = idx & 15;
        Kh[m * KH_STR + dp] = kg[idx];
    }
    for (int idx = tid; idx < (NTOK / 2) * DH; idx += 256) {
        int mp = idx >> 5, d = idx & 31;
        float v0 = vg[(2 * mp)     * DH + d];
        float v1 = vg[(2 * mp + 1) * DH + d];
        Vh[d * V_STR2 + mp] = packh2(v0, v1);
    }
    int wt = win >> 6, wh = (win >> 3) & 7, ww = win & 7;
    for (int nn = tid; nn < NTOK; nn += 256) {
        int i = nn / 49, rem = nn - i * 49, j = rem / 7, k2 = rem - j * 7;
        int z = wt * 8 + i, y = wh * 7 + j, xx = ww * 7 + k2;
        int lt = (z  < 8)  ? 0 : ((z  < 12) ? 1 : 2);
        int lh = (y  < 49) ? 0 : ((y  < 53) ? 1 : 2);
        int lw = (xx < 49) ? 0 : ((xx < 53) ? 1 : 2);
        lb[nn] = lt * 9 + lh * 3 + lw;
    }
    __syncthreads();

    int w = tid >> 5, lane = tid & 31;
    int g = lane >> 2, t4 = lane & 3;
    const __half* brow = g_biash + (size_t)head * NTOK * NTOK;
    int mofs = 2 * t4;

    for (int qt = w; qt < 25; qt += 8) {
        int q0r = qt * 16;
        int n_g  = q0r + g;
        int n_g8 = n_g + 8;
        int nc_g  = (n_g  < NTOK) ? n_g  : NTOK - 1;
        int nc_g8 = (n_g8 < NTOK) ? n_g8 : NTOK - 1;
        int lbn_g  = lb[nc_g];
        int lbn_g8 = lb[nc_g8];
        const __half* bp_g  = brow + (size_t)nc_g  * NTOK;
        const __half* bp_g8 = brow + (size_t)nc_g8 * NTOK;

        unsigned qa0[4], qa1[4];
        {
            const unsigned* qb  = qg + (size_t)(q0r + g) * 16;
            const unsigned* qb8 = qb + 8 * 16;
            qa0[0] = qb [t4];      qa0[1] = qb8[t4];
            qa0[2] = qb [t4 + 4];  qa0[3] = qb8[t4 + 4];
            qa1[0] = qb [t4 + 8];  qa1[1] = qb8[t4 + 8];
            qa1[2] = qb [t4 + 12]; qa1[3] = qb8[t4 + 12];
        }

        float o[4][4] = {};
        float sacc[4] = {};

        float2 pb0g  = __half22float2(*(const __half2*)(bp_g  + mofs));
        float2 pb1g  = __half22float2(*(const __half2*)(bp_g  + 8 + mofs));
        float2 pb0g8 = __half22float2(*(const __half2*)(bp_g8 + mofs));
        float2 pb1g8 = __half22float2(*(const __half2*)(bp_g8 + 8 + mofs));

        for (int jp = 0; jp < 24; ++jp) {
            int j0 = jp * 2, j1 = j0 + 1;
            float2 b0g = pb0g, b1g = pb1g, b0g8 = pb0g8, b1g8 = pb1g8;
            {
                int nj = (jp < 23) ? (j0 + 2) : 48;
                pb0g  = __half22float2(*(const __half2*)(bp_g  + nj * 8 + mofs));
                pb0g8 = __half22float2(*(const __half2*)(bp_g8 + nj * 8 + mofs));
                if (jp < 23) {
                    pb1g  = __half22float2(*(const __half2*)(bp_g  + nj * 8 + 8 + mofs));
                    pb1g8 = __half22float2(*(const __half2*)(bp_g8 + nj * 8 + 8 + mofs));
                }
            }

            float c0[4] = {0.f, 0.f, 0.f, 0.f};
            float c1[4] = {0.f, 0.f, 0.f, 0.f};
            {
                const unsigned* kr0 = Kh + (j0 * 8 + g) * KH_STR;
                const unsigned* kr1 = Kh + (j1 * 8 + g) * KH_STR;
                mma16h(c0, qa0[0], qa0[1], qa0[2], qa0[3], kr0[t4],     kr0[t4 + 4]);
                mma16h(c0, qa1[0], qa1[1], qa1[2], qa1[3], kr0[t4 + 8], kr0[t4 + 12]);
                mma16h(c1, qa0[0], qa0[1], qa0[2], qa0[3], kr1[t4],     kr1[t4 + 4]);
                mma16h(c1, qa1[0], qa1[1], qa1[2], qa1[3], kr1[t4 + 8], kr1[t4 + 12]);
            }

            int m0 = j0 * 8 + mofs, m1 = j1 * 8 + mofs;
            int lm00 = lb[m0], lm01 = lb[m0 + 1];
            int lm10 = lb[m1], lm11 = lb[m1 + 1];

            float s00 = c0[0] + b0g.x  + ((lm00 != lbn_g)  ? MASKC : 0.f);
            float s01 = c0[1] + b0g.y  + ((lm01 != lbn_g)  ? MASKC : 0.f);
            float s02 = c0[2] + b0g8.x + ((lm00 != lbn_g8) ? MASKC : 0.f);
            float s03 = c0[3] + b0g8.y + ((lm01 != lbn_g8) ? MASKC : 0.f);
            float s10 = c1[0] + b1g.x  + ((lm10 != lbn_g)  ? MASKC : 0.f);
            float s11 = c1[1] + b1g.y  + ((lm11 != lbn_g)  ? MASKC : 0.f);
            float s12 = c1[2] + b1g8.x + ((lm10 != lbn_g8) ? MASKC : 0.f);
            float s13 = c1[3] + b1g8.y + ((lm11 != lbn_g8) ? MASKC : 0.f);

            unsigned a0 = h2exp2(packh2(s00, s01));
            unsigned a1 = h2exp2(packh2(s02, s03));
            unsigned a2 = h2exp2(packh2(s10, s11));
            unsigned a3 = h2exp2(packh2(s12, s13));

            mma16h(sacc, a0, a1, a2, a3, ONES2, ONES2);

            #pragma unroll
            for (int jd = 0; jd < 4; ++jd) {
                int vrow = (jd * 8 + g) * V_STR2 + j0 * 4 + t4;
                mma16h(o[jd], a0, a1, a2, a3, Vh[vrow], Vh[vrow + 4]);
            }
        }

        // tail tile j=48 (k=8..15 zeroed on BOTH operands)
        {
            const int j = 48;
            float c[4] = {0.f, 0.f, 0.f, 0.f};
            const unsigned* kr = Kh + (j * 8 + g) * KH_STR;
            mma16h(c, qa0[0], qa0[1], qa0[2], qa0[3], kr[t4],     kr[t4 + 4]);
            mma16h(c, qa1[0], qa1[1], qa1[2], qa1[3], kr[t4 + 8], kr[t4 + 12]);

            int m0 = j * 8 + mofs;
            int lm0 = lb[m0], lm1 = lb[m0 + 1];
            float s0 = c[0] + pb0g.x  + ((lm0 != lbn_g)  ? MASKC : 0.f);
            float s1 = c[1] + pb0g.y  + ((lm1 != lbn_g)  ? MASKC : 0.f);
            float s2 = c[2] + pb0g8.x + ((lm0 != lbn_g8) ? MASKC : 0.f);
            float s3 = c[3] + pb0g8.y + ((lm1 != lbn_g8) ? MASKC : 0.f);

            unsigned a0 = h2exp2(packh2(s0, s1));
            unsigned a1 = h2exp2(packh2(s2, s3));

            mma16h(sacc, a0, a1, 0u, 0u, ONES2, ONES2);

            #pragma unroll
            for (int jd = 0; jd < 4; ++jd) {
                int vrow = (jd * 8 + g) * V_STR2 + j * 4 + t4;
                mma16h(o[jd], a0, a1, 0u, 0u, Vh[vrow], 0u);
            }
        }

        float inv_g  = 1.f / sacc[0];
        float inv_g8 = 1.f / sacc[2];

        if (n_g < NTOK) {
            unsigned* ob = g_aoh + (size_t)(win * NTOK + n_g) * 128 + head * 16;
            #pragma unroll
            for (int jd = 0; jd < 4; ++jd)
                ob[jd * 4 + t4] = packh2(o[jd][0] * inv_g, o[jd][1] * inv_g);
        }
        if (n_g8 < NTOK) {
            unsigned* ob = g_aoh + (size_t)(win * NTOK + n_g8) * 128 + head * 16;
            #pragma unroll
            for (int jd = 0; jd < 4; ++jd)
                ob[jd * 4 + t4] = packh2(o[jd][2] * inv_g8, o[jd][3] * inv_g8);
        }
    }
}

// ---------------------------------------------------------------------------
// Projection GEMM (fp16): BM=128, BN=128, 512 threads. A = g_aoh, B = g_wp_h.
// Fused reverse-window + reverse-roll scatter.
// ---------------------------------------------------------------------------
__global__ void __launch_bounds__(512, 2) proj_gemm(
    const float* __restrict__ bp, float* __restrict__ out)
{
    __shared__ __align__(16) unsigned As[2][128 * HA_STR];
    __shared__ __align__(16) unsigned Bs[2][8 * HB2_STR];

    int tid  = threadIdx.x;
    int row0 = blockIdx.x * 128;
    int col0 = blockIdx.y * 128;
    int lr   = tid >> 2, kq = tid & 3;

    const unsigned* ap = g_aoh + (size_t)(row0 + lr) * 128 + kq * 2;
    int bkr  = tid >> 6;
    int bnc2 = (tid & 63) * 2;
    const unsigned* wsrc = g_wp_h + col0 + bnc2;

    int warp = tid >> 5, lane = tid & 31;
    int wm = warp >> 2, wn = warp & 3;
    int g = lane >> 2, t4 = lane & 3;

    float acc[2][4][4] = {};

    {
        uint2 a0 = *(const uint2*)(ap);
        uint2 bv = *(const uint2*)(wsrc + bkr * CCH);
        *(uint2*)&As[0][lr * HA_STR + kq * 2]  = a0;
        *(uint2*)&Bs[0][bkr * HB2_STR + bnc2]  = bv;
    }
    __syncthreads();

    for (int kt = 0; kt < 16; ++kt) {
        int buf = kt & 1;
        uint2 a0n, bvn;
        if (kt < 15) {
            a0n = *(const uint2*)(ap + (kt + 1) * 8);
            bvn = *(const uint2*)(wsrc + ((kt + 1) * 8 + bkr) * CCH);
        }
        unsigned afr[2][4], bfr[4][2];
        #pragma unroll
        for (int mt = 0; mt < 2; ++mt) {
            int m0 = wm * 32 + mt * 16;
            const unsigned* base = &As[buf][0];
            afr[mt][0] = base[(m0 + g)     * HA_STR + t4];
            afr[mt][1] = base[(m0 + g + 8) * HA_STR + t4];
            afr[mt][2] = base[(m0 + g)     * HA_STR + t4 + 4];
            afr[mt][3] = base[(m0 + g + 8) * HA_STR + t4 + 4];
        }
        #pragma unroll
        for (int nt = 0; nt < 4; ++nt) {
            int n0 = wn * 32 + nt * 8;
            bfr[nt][0] = Bs[buf][t4 * HB2_STR + n0 + g];
            bfr[nt][1] = Bs[buf][(t4 + 4) * HB2_STR + n0 + g];
        }
        #pragma unroll
        for (int mt = 0; mt < 2; ++mt)
            #pragma unroll
            for (int nt = 0; nt < 4; ++nt)
                mma16h(acc[mt][nt], afr[mt][0], afr[mt][1], afr[mt][2],
                       afr[mt][3], bfr[nt][0], bfr[nt][1]);

        if (kt < 15) {
            int nb = buf ^ 1;
            *(uint2*)&As[nb][lr * HA_STR + kq * 2] = a0n;
            *(uint2*)&Bs[nb][bkr * HB2_STR + bnc2] = bvn;
            __syncthreads();
        }
    }

    #pragma unroll
    for (int mt = 0; mt < 2; ++mt) {
        #pragma unroll
        for (int half = 0; half < 2; ++half) {
            int rg  = row0 + wm * 32 + mt * 16 + g + half * 8;
            int win = rg / NTOK, n = rg - win * NTOK;
            int wt = win >> 6, wh = (win >> 3) & 7, ww = win & 7;
            int i = n / 49, rem = n - i * 49, j = rem / 7, kk = rem - j * 7;
            int z  = (wt * 8 + i + 4) & 15;
            int y  = wh * 7 + j + 3;  if (y  >= 56) y  -= 56;
            int xx = ww * 7 + kk + 3; if (xx >= 56) xx -= 56;
            float* dst = out + (((z * 56 + y) * 56 + xx) << 8);
            #pragma unroll
            for (int nt = 0; nt < 4; ++nt) {
                int c = col0 + wn * 32 + nt * 8 + 2 * t4;
                float v0 = acc[mt][nt][half * 2 + 0] + bp[c];
                float v1 = acc[mt][nt][half * 2 + 1] + bp[c + 1];
                *(float2*)&dst[c] = make_float2(v0, v1);
            }
        }
    }
}

// ---------------------------------------------------------------------------
extern "C" void kernel_launch(void* const* d_in, const int* in_sizes, int n_in,
                              void* d_out, int out_size)
{
    (void)in_sizes; (void)n_in; (void)out_size;
    const float* x      = (const float*)d_in[0];
    const float* qkv_w  = (const float*)d_in[1];
    const float* qkv_b  = (const float*)d_in[2];
    const float* proj_w = (const float*)d_in[3];
    const float* proj_b = (const float*)d_in[4];
    const float* rpb    = (const float*)d_in[5];
    float* out = (float*)d_out;

    cudaFuncSetAttribute(attn_kernel,
                         cudaFuncAttributeMaxDynamicSharedMemorySize,
                         ATTN_SMEM_BYTES);

    bias_kernel<<<(NHD * NTOK * NTOK + 255) / 256, 256>>>(rpb);
    cvt_w_kernel<<<(128 * QKVN + 128 * CCH + 255) / 256, 256>>>(qkv_w, proj_w);

    dim3 gq(MROWS / 128, QKVN / 128);
    qkv_gemm<<<gq, 512>>>(x, qkv_b);

    attn_kernel<<<NWIN * NHD, 256, ATTN_SMEM_BYTES>>>();

    dim3 gp(MROWS / 128, CCH / 128);
    proj_gemm<<<gp, 512>>>(proj_b, out);
}

// round 15
// speedup vs baseline: 1.1444x; 1.0172x over previous
#include <cuda_runtime.h>
#include <cuda_fp16.h>

// ---------------------------------------------------------------------------
// Shifted-window 3D attention — all-fp16 tensor-core pipeline (fp32 accum).
// Round 15: attn pushed to 4 blocks/SM (char labels for smem, no bias
// prefetch registers -> 64-reg budget). GEMMs identical to round 14.
// ---------------------------------------------------------------------------

#define NWIN   128
#define NTOK   392
#define NHD    8
#define DH     32
#define CCH    256
#define MROWS  (NWIN * NTOK)        // 50176
#define QKVN   768

#define LOG2E  1.4426950408889634f
#define MASKC  (-144.26950408889634f)   // -100 * log2(e)
#define ONES2  0x3C003C00u              // half2(1.0, 1.0)

// Scratch (device globals). g_qh padded 8 rows (128 uints) for the last
// q-tile over-read.
__device__ unsigned g_qh [NWIN * NHD * NTOK * (DH / 2) + 128]; // q fp16 pairs
__device__ unsigned g_kh [NWIN * NHD * NTOK * (DH / 2)];       // k fp16 pairs
__device__ float    g_v  [NWIN * NHD * NTOK * DH];
__device__ unsigned g_aoh[MROWS * (CCH / 2)];                  // attn out, fp16 pairs
__device__ __half   g_biash[NHD * NTOK * NTOK];
__device__ unsigned g_wq_h[(256 / 2) * QKVN];   // qkv_w fp16 pairs, [k/2][n]
__device__ unsigned g_wp_h[(256 / 2) * CCH];    // proj_w fp16 pairs, [k/2][n]

__device__ __forceinline__ void mma16h(float* c, unsigned a0, unsigned a1,
                                       unsigned a2, unsigned a3,
                                       unsigned b0, unsigned b1) {
    asm volatile(
        "mma.sync.aligned.m16n8k16.row.col.f32.f16.f16.f32 "
        "{%0,%1,%2,%3},{%4,%5,%6,%7},{%8,%9},{%0,%1,%2,%3};"
        : "+f"(c[0]), "+f"(c[1]), "+f"(c[2]), "+f"(c[3])
        : "r"(a0), "r"(a1), "r"(a2), "r"(a3), "r"(b0), "r"(b1));
}

__device__ __forceinline__ unsigned packh2(float lo, float hi) {
    __half2 h = __floats2half2_rn(lo, hi);
    return *(unsigned*)&h;
}

__device__ __forceinline__ unsigned h2exp2(unsigned x) {
    unsigned r;
    asm("ex2.approx.f16x2 %0, %1;" : "=r"(r) : "r"(x));
    return r;
}

// ---------------------------------------------------------------------------
// Relative-position bias precompute (log2e-scaled, fp16).
// ---------------------------------------------------------------------------
__global__ void bias_kernel(const float* __restrict__ rpb) {
    int idx = blockIdx.x * 256 + threadIdx.x;
    if (idx >= NHD * NTOK * NTOK) return;
    int m = idx % NTOK;
    int t = idx / NTOK;
    int n = t % NTOK;
    int h = t / NTOK;
    int i1 = n / 49, r1 = n - i1 * 49, j1 = r1 / 7, k1 = r1 - j1 * 7;
    int i2 = m / 49, r2 = m - i2 * 49, j2 = r2 / 7, k2 = r2 - j2 * 7;
    int tb = (i1 - i2 + 7) * 169 + (j1 - j2 + 6) * 13 + (k1 - k2 + 6);
    g_biash[idx] = __float2half(rpb[tb * 8 + h] * LOG2E);
}

// Weight pre-convert: fp32 [n][k] -> fp16 k-pairs [k/2][n]
__global__ void cvt_w_kernel(const float* __restrict__ wq,
                             const float* __restrict__ wp) {
    int idx = blockIdx.x * 256 + threadIdx.x;
    if (idx < 128 * QKVN) {
        int kp = idx / QKVN, n = idx - kp * QKVN;
        g_wq_h[idx] = packh2(wq[n * 256 + 2 * kp], wq[n * 256 + 2 * kp + 1]);
    } else {
        int i2 = idx - 128 * QKVN;
        if (i2 < 128 * CCH) {
            int kp = i2 >> 8, n = i2 & 255;
            g_wp_h[i2] = packh2(wp[n * 256 + 2 * kp], wp[n * 256 + 2 * kp + 1]);
        }
    }
}

// ---------------------------------------------------------------------------
// fp16 GEMM tiles: BM=128, BN=128, BK=16, 512 threads (16 warps, 32x32 each).
// ---------------------------------------------------------------------------
#define HA_STR  12
#define HB2_STR 136

__global__ void __launch_bounds__(512, 2) qkv_gemm(
    const float* __restrict__ x, const float* __restrict__ bq)
{
    __shared__ __align__(16) unsigned As[2][128 * HA_STR];
    __shared__ __align__(16) unsigned Bs[2][8 * HB2_STR];

    int tid  = threadIdx.x;
    int row0 = blockIdx.x * 128;
    int col0 = blockIdx.y * 128;
    int lr   = tid >> 2, kq = tid & 3;

    const float* ap;
    {
        int r   = row0 + lr;
        int win = r / NTOK, n = r - win * NTOK;
        int wt = win >> 6, wh = (win >> 3) & 7, ww = win & 7;
        int i = n / 49, rem = n - i * 49, j = rem / 7, kk = rem - j * 7;
        int z  = (wt * 8 + i + 4) & 15;
        int y  = wh * 7 + j + 3;  if (y  >= 56) y  -= 56;
        int xx = ww * 7 + kk + 3; if (xx >= 56) xx -= 56;
        ap = x + (((z * 56 + y) * 56 + xx) << 8) + (kq << 2);
    }
    int bkr  = tid >> 6;            // 0..7  (k-pair row)
    int bnc2 = (tid & 63) * 2;      // 0..126
    const unsigned* wsrc = g_wq_h + col0 + bnc2;

    int warp = tid >> 5, lane = tid & 31;
    int wm = warp >> 2, wn = warp & 3;
    int g = lane >> 2, t4 = lane & 3;

    float acc[2][4][4] = {};

    {
        float4 a0 = *(const float4*)(ap);
        uint2  bv = *(const uint2*)(wsrc + bkr * QKVN);
        As[0][lr * HA_STR + kq * 2]     = packh2(a0.x, a0.y);
        As[0][lr * HA_STR + kq * 2 + 1] = packh2(a0.z, a0.w);
        *(uint2*)&Bs[0][bkr * HB2_STR + bnc2] = bv;
    }
    __syncthreads();

    for (int kt = 0; kt < 16; ++kt) {
        int buf = kt & 1;
        float4 a0n;
        uint2  bvn;
        if (kt < 15) {
            a0n = *(const float4*)(ap + (kt + 1) * 16);
            bvn = *(const uint2*)(wsrc + ((kt + 1) * 8 + bkr) * QKVN);
        }
        unsigned afr[2][4], bfr[4][2];
        #pragma unroll
        for (int mt = 0; mt < 2; ++mt) {
            int m0 = wm * 32 + mt * 16;
            const unsigned* base = &As[buf][0];
            afr[mt][0] = base[(m0 + g)     * HA_STR + t4];
            afr[mt][1] = base[(m0 + g + 8) * HA_STR + t4];
            afr[mt][2] = base[(m0 + g)     * HA_STR + t4 + 4];
            afr[mt][3] = base[(m0 + g + 8) * HA_STR + t4 + 4];
        }
        #pragma unroll
        for (int nt = 0; nt < 4; ++nt) {
            int n0 = wn * 32 + nt * 8;
            bfr[nt][0] = Bs[buf][t4 * HB2_STR + n0 + g];
            bfr[nt][1] = Bs[buf][(t4 + 4) * HB2_STR + n0 + g];
        }
        #pragma unroll
        for (int mt = 0; mt < 2; ++mt)
            #pragma unroll
            for (int nt = 0; nt < 4; ++nt)
                mma16h(acc[mt][nt], afr[mt][0], afr[mt][1], afr[mt][2],
                       afr[mt][3], bfr[nt][0], bfr[nt][1]);

        if (kt < 15) {
            int nb = buf ^ 1;
            As[nb][lr * HA_STR + kq * 2]     = packh2(a0n.x, a0n.y);
            As[nb][lr * HA_STR + kq * 2 + 1] = packh2(a0n.z, a0n.w);
            *(uint2*)&Bs[nb][bkr * HB2_STR + bnc2] = bvn;
            __syncthreads();
        }
    }

    int part = col0 >> 8;
    float scale = (part == 0) ? (0.17677669529663687f * LOG2E) : 1.0f;
    #pragma unroll
    for (int mt = 0; mt < 2; ++mt) {
        #pragma unroll
        for (int half = 0; half < 2; ++half) {
            int rg  = row0 + wm * 32 + mt * 16 + g + half * 8;
            int win = rg / NTOK, n = rg - win * NTOK;
            #pragma unroll
            for (int nt = 0; nt < 4; ++nt) {
                int c = col0 + wn * 32 + nt * 8 + 2 * t4;
                int head = (c >> 5) & 7, d = c & 31;
                float r0 = (acc[mt][nt][half * 2 + 0] + bq[c])     * scale;
                float r1 = (acc[mt][nt][half * 2 + 1] + bq[c + 1]) * scale;
                size_t bhn = ((size_t)(win * 8 + head) * NTOK + n);
                if (part < 2) {
                    unsigned* dsth = (part == 0) ? g_qh : g_kh;
                    dsth[bhn * 16 + (d >> 1)] = packh2(r0, r1);
                } else {
                    *(float2*)&g_v[bhn * 32 + d] = make_float2(r0, r1);
                }
            }
        }
    }
}

// ---------------------------------------------------------------------------
// Flash attention: 4 blocks/SM (char labels, no bias prefetch regs),
// fp16x2 exp2 softmax, ones-mma row sums.
// ---------------------------------------------------------------------------
#define KH_STR 20
#define V_STR2 196
#define ATTN_SMEM_BYTES (((NTOK * KH_STR + 32 * V_STR2 + 8) * 4) + NTOK + 8)

__global__ void __launch_bounds__(256, 4) attn_kernel() {
    extern __shared__ float sm[];
    unsigned* Kh = (unsigned*)sm;
    unsigned* Vh = Kh + NTOK * KH_STR;
    char*     lb = (char*)(Vh + 32 * V_STR2 + 8);

    int tid = threadIdx.x;
    int bh  = blockIdx.x;
    int win = bh >> 3, head = bh & 7;

    const unsigned* kg = g_kh + (size_t)bh * NTOK * 16;
    const float*    vg = g_v  + (size_t)bh * NTOK * DH;
    const unsigned* qg = g_qh + (size_t)bh * NTOK * 16;

    for (int idx = tid; idx < NTOK * 16; idx += 256) {
        int m = idx >> 4, dp = idx & 15;
        Kh[m * KH_STR + dp] = kg[idx];
    }
    for (int idx = tid; idx < (NTOK / 2) * DH; idx += 256) {
        int mp = idx >> 5, d = idx & 31;
        float v0 = vg[(2 * mp)     * DH + d];
        float v1 = vg[(2 * mp + 1) * DH + d];
        Vh[d * V_STR2 + mp] = packh2(v0, v1);
    }
    int wt = win >> 6, wh = (win >> 3) & 7, ww = win & 7;
    for (int nn = tid; nn < NTOK; nn += 256) {
        int i = nn / 49, rem = nn - i * 49, j = rem / 7, k2 = rem - j * 7;
        int z = wt * 8 + i, y = wh * 7 + j, xx = ww * 7 + k2;
        int lt = (z  < 8)  ? 0 : ((z  < 12) ? 1 : 2);
        int lh = (y  < 49) ? 0 : ((y  < 53) ? 1 : 2);
        int lw = (xx < 49) ? 0 : ((xx < 53) ? 1 : 2);
        lb[nn] = (char)(lt * 9 + lh * 3 + lw);
    }
    __syncthreads();

    int w = tid >> 5, lane = tid & 31;
    int g = lane >> 2, t4 = lane & 3;
    const __half* brow = g_biash + (size_t)head * NTOK * NTOK;
    int mofs = 2 * t4;

    for (int qt = w; qt < 25; qt += 8) {
        int q0r = qt * 16;
        int n_g  = q0r + g;
        int n_g8 = n_g + 8;
        int nc_g  = (n_g  < NTOK) ? n_g  : NTOK - 1;
        int nc_g8 = (n_g8 < NTOK) ? n_g8 : NTOK - 1;
        int lbn_g  = lb[nc_g];
        int lbn_g8 = lb[nc_g8];
        const __half* bp_g  = brow + (size_t)nc_g  * NTOK + mofs;
        const __half* bp_g8 = brow + (size_t)nc_g8 * NTOK + mofs;

        unsigned qa0[4], qa1[4];
        {
            const unsigned* qb  = qg + (size_t)(q0r + g) * 16;
            const unsigned* qb8 = qb + 8 * 16;
            qa0[0] = qb [t4];      qa0[1] = qb8[t4];
            qa0[2] = qb [t4 + 4];  qa0[3] = qb8[t4 + 4];
            qa1[0] = qb [t4 + 8];  qa1[1] = qb8[t4 + 8];
            qa1[2] = qb [t4 + 12]; qa1[3] = qb8[t4 + 12];
        }

        float o[4][4] = {};
        float sacc[4] = {};

        for (int jp = 0; jp < 24; ++jp) {
            int j0 = jp * 2, j1 = j0 + 1;

            // bias loads (mma-independent; issue early, consumed post-mma)
            float2 b0g  = __half22float2(*(const __half2*)(bp_g  + j0 * 8));
            float2 b1g  = __half22float2(*(const __half2*)(bp_g  + j1 * 8));
            float2 b0g8 = __half22float2(*(const __half2*)(bp_g8 + j0 * 8));
            float2 b1g8 = __half22float2(*(const __half2*)(bp_g8 + j1 * 8));

            float c0[4] = {0.f, 0.f, 0.f, 0.f};
            float c1[4] = {0.f, 0.f, 0.f, 0.f};
            {
                const unsigned* kr0 = Kh + (j0 * 8 + g) * KH_STR;
                const unsigned* kr1 = Kh + (j1 * 8 + g) * KH_STR;
                mma16h(c0, qa0[0], qa0[1], qa0[2], qa0[3], kr0[t4],     kr0[t4 + 4]);
                mma16h(c0, qa1[0], qa1[1], qa1[2], qa1[3], kr0[t4 + 8], kr0[t4 + 12]);
                mma16h(c1, qa0[0], qa0[1], qa0[2], qa0[3], kr1[t4],     kr1[t4 + 4]);
                mma16h(c1, qa1[0], qa1[1], qa1[2], qa1[3], kr1[t4 + 8], kr1[t4 + 12]);
            }

            int m0 = j0 * 8 + mofs, m1 = j1 * 8 + mofs;
            int lm00 = lb[m0], lm01 = lb[m0 + 1];
            int lm10 = lb[m1], lm11 = lb[m1 + 1];

            float s00 = c0[0] + b0g.x  + ((lm00 != lbn_g)  ? MASKC : 0.f);
            float s01 = c0[1] + b0g.y  + ((lm01 != lbn_g)  ? MASKC : 0.f);
            float s02 = c0[2] + b0g8.x + ((lm00 != lbn_g8) ? MASKC : 0.f);
            float s03 = c0[3] + b0g8.y + ((lm01 != lbn_g8) ? MASKC : 0.f);
            float s10 = c1[0] + b1g.x  + ((lm10 != lbn_g)  ? MASKC : 0.f);
            float s11 = c1[1] + b1g.y  + ((lm11 != lbn_g)  ? MASKC : 0.f);
            float s12 = c1[2] + b1g8.x + ((lm10 != lbn_g8) ? MASKC : 0.f);
            float s13 = c1[3] + b1g8.y + ((lm11 != lbn_g8) ? MASKC : 0.f);

            unsigned a0 = h2exp2(packh2(s00, s01));
            unsigned a1 = h2exp2(packh2(s02, s03));
            unsigned a2 = h2exp2(packh2(s10, s11));
            unsigned a3 = h2exp2(packh2(s12, s13));

            mma16h(sacc, a0, a1, a2, a3, ONES2, ONES2);

            #pragma unroll
            for (int jd = 0; jd < 4; ++jd) {
                int vrow = (jd * 8 + g) * V_STR2 + j0 * 4 + t4;
                mma16h(o[jd], a0, a1, a2, a3, Vh[vrow], Vh[vrow + 4]);
            }
        }

        // tail tile j=48 (k=8..15 zeroed on BOTH operands)
        {
            const int j = 48;
            float2 b0g  = __half22float2(*(const __half2*)(bp_g  + j * 8));
            float2 b0g8 = __half22float2(*(const __half2*)(bp_g8 + j * 8));

            float c[4] = {0.f, 0.f, 0.f, 0.f};
            const unsigned* kr = Kh + (j * 8 + g) * KH_STR;
            mma16h(c, qa0[0], qa0[1], qa0[2], qa0[3], kr[t4],     kr[t4 + 4]);
            mma16h(c, qa1[0], qa1[1], qa1[2], qa1[3], kr[t4 + 8], kr[t4 + 12]);

            int m0 = j * 8 + mofs;
            int lm0 = lb[m0], lm1 = lb[m0 + 1];
            float s0 = c[0] + b0g.x  + ((lm0 != lbn_g)  ? MASKC : 0.f);
            float s1 = c[1] + b0g.y  + ((lm1 != lbn_g)  ? MASKC : 0.f);
            float s2 = c[2] + b0g8.x + ((lm0 != lbn_g8) ? MASKC : 0.f);
            float s3 = c[3] + b0g8.y + ((lm1 != lbn_g8) ? MASKC : 0.f);

            unsigned a0 = h2exp2(packh2(s0, s1));
            unsigned a1 = h2exp2(packh2(s2, s3));

            mma16h(sacc, a0, a1, 0u, 0u, ONES2, ONES2);

            #pragma unroll
            for (int jd = 0; jd < 4; ++jd) {
                int vrow = (jd * 8 + g) * V_STR2 + j * 4 + t4;
                mma16h(o[jd], a0, a1, 0u, 0u, Vh[vrow], 0u);
            }
        }

        float inv_g  = 1.f / sacc[0];
        float inv_g8 = 1.f / sacc[2];

        if (n_g < NTOK) {
            unsigned* ob = g_aoh + (size_t)(win * NTOK + n_g) * 128 + head * 16;
            #pragma unroll
            for (int jd = 0; jd < 4; ++jd)
                ob[jd * 4 + t4] = packh2(o[jd][0] * inv_g, o[jd][1] * inv_g);
        }
        if (n_g8 < NTOK) {
            unsigned* ob = g_aoh + (size_t)(win * NTOK + n_g8) * 128 + head * 16;
            #pragma unroll
            for (int jd = 0; jd < 4; ++jd)
                ob[jd * 4 + t4] = packh2(o[jd][2] * inv_g8, o[jd][3] * inv_g8);
        }
    }
}

// ---------------------------------------------------------------------------
// Projection GEMM (fp16): BM=128, BN=128, 512 threads. A = g_aoh, B = g_wp_h.
// ---------------------------------------------------------------------------
__global__ void __launch_bounds__(512, 2) proj_gemm(
    const float* __restrict__ bp, float* __restrict__ out)
{
    __shared__ __align__(16) unsigned As[2][128 * HA_STR];
    __shared__ __align__(16) unsigned Bs[2][8 * HB2_STR];

    int tid  = threadIdx.x;
    int row0 = blockIdx.x * 128;
    int col0 = blockIdx.y * 128;
    int lr   = tid >> 2, kq = tid & 3;

    const unsigned* ap = g_aoh + (size_t)(row0 + lr) * 128 + kq * 2;
    int bkr  = tid >> 6;
    int bnc2 = (tid & 63) * 2;
    const unsigned* wsrc = g_wp_h + col0 + bnc2;

    int warp = tid >> 5, lane = tid & 31;
    int wm = warp >> 2, wn = warp & 3;
    int g = lane >> 2, t4 = lane & 3;

    float acc[2][4][4] = {};

    {
        uint2 a0 = *(const uint2*)(ap);
        uint2 bv = *(const uint2*)(wsrc + bkr * CCH);
        *(uint2*)&As[0][lr * HA_STR + kq * 2]  = a0;
        *(uint2*)&Bs[0][bkr * HB2_STR + bnc2]  = bv;
    }
    __syncthreads();

    for (int kt = 0; kt < 16; ++kt) {
        int buf = kt & 1;
        uint2 a0n, bvn;
        if (kt < 15) {
            a0n = *(const uint2*)(ap + (kt + 1) * 8);
            bvn = *(const uint2*)(wsrc + ((kt + 1) * 8 + bkr) * CCH);
        }
        unsigned afr[2][4], bfr[4][2];
        #pragma unroll
        for (int mt = 0; mt < 2; ++mt) {
            int m0 = wm * 32 + mt * 16;
            const unsigned* base = &As[buf][0];
            afr[mt][0] = base[(m0 + g)     * HA_STR + t4];
            afr[mt][1] = base[(m0 + g + 8) * HA_STR + t4];
            afr[mt][2] = base[(m0 + g)     * HA_STR + t4 + 4];
            afr[mt][3] = base[(m0 + g + 8) * HA_STR + t4 + 4];
        }
        #pragma unroll
        for (int nt = 0; nt < 4; ++nt) {
            int n0 = wn * 32 + nt * 8;
            bfr[nt][0] = Bs[buf][t4 * HB2_STR + n0 + g];
            bfr[nt][1] = Bs[buf][(t4 + 4) * HB2_STR + n0 + g];
        }
        #pragma unroll
        for (int mt = 0; mt < 2; ++mt)
            #pragma unroll
            for (int nt = 0; nt < 4; ++nt)
                mma16h(acc[mt][nt], afr[mt][0], afr[mt][1], afr[mt][2],
                       afr[mt][3], bfr[nt][0], bfr[nt][1]);

        if (kt < 15) {
            int nb = buf ^ 1;
            *(uint2*)&As[nb][lr * HA_STR + kq * 2] = a0n;
            *(uint2*)&Bs[nb][bkr * HB2_STR + bnc2] = bvn;
            __syncthreads();
        }
    }

    #pragma unroll
    for (int mt = 0; mt < 2; ++mt) {
        #pragma unroll
        for (int half = 0; half < 2; ++half) {
            int rg  = row0 + wm * 32 + mt * 16 + g + half * 8;
            int win = rg / NTOK, n = rg - win * NTOK;
            int wt = win >> 6, wh = (win >> 3) & 7, ww = win & 7;
            int i = n / 49, rem = n - i * 49, j = rem / 7, kk = rem - j * 7;
            int z  = (wt * 8 + i + 4) & 15;
            int y  = wh * 7 + j + 3;  if (y  >= 56) y  -= 56;
            int xx = ww * 7 + kk + 3; if (xx >= 56) xx -= 56;
            float* dst = out + (((z * 56 + y) * 56 + xx) << 8);
            #pragma unroll
            for (int nt = 0; nt < 4; ++nt) {
                int c = col0 + wn * 32 + nt * 8 + 2 * t4;
                float v0 = acc[mt][nt][half * 2 + 0] + bp[c];
                float v1 = acc[mt][nt][half * 2 + 1] + bp[c + 1];
                *(float2*)&dst[c] = make_float2(v0, v1);
            }
        }
    }
}

// ---------------------------------------------------------------------------
extern "C" void kernel_launch(void* const* d_in, const int* in_sizes, int n_in,
                              void* d_out, int out_size)
{
    (void)in_sizes; (void)n_in; (void)out_size;
    const float* x      = (const float*)d_in[0];
    const float* qkv_w  = (const float*)d_in[1];
    const float* qkv_b  = (const float*)d_in[2];
    const float* proj_w = (const float*)d_in[3];
    const float* proj_b = (const float*)d_in[4];
    const float* rpb    = (const float*)d_in[5];
    float* out = (float*)d_out;

    cudaFuncSetAttribute(attn_kernel,
                         cudaFuncAttributeMaxDynamicSharedMemorySize,
                         ATTN_SMEM_BYTES);

    bias_kernel<<<(NHD * NTOK * NTOK + 255) / 256, 256>>>(rpb);
    cvt_w_kernel<<<(128 * QKVN + 128 * CCH + 255) / 256, 256>>>(qkv_w, proj_w);

    dim3 gq(MROWS / 128, QKVN / 128);
    qkv_gemm<<<gq, 512>>>(x, qkv_b);

    attn_kernel<<<NWIN * NHD, 256, ATTN_SMEM_BYTES>>>();

    dim3 gp(MROWS / 128, CCH / 128);
    proj_gemm<<<gp, 512>>>(proj_b, out);
}